// round 10
// baseline (speedup 1.0000x reference)
#include <cuda_runtime.h>
#include <cuda_bf16.h>
#include <math.h>
#include <stdint.h>

// Problem constants
#define B_   128
#define T_   2048
#define H_   200
#define NS_  5

#define BMT  128                        // enc rows per K1 block
#define NT_TC (B_ * T_ / BMT)           // 2048 blocks
#define TPB_TC (T_ / BMT)               // 16 tiles per batch
#define AS   108                        // A smem row stride (32-bit words)
#define BSW  12                         // B smem row stride (32-bit words)
#define NCHUNK 13                       // ceil(200/16)

// Scratch (static device globals — no dynamic allocation)
__device__ float g_qproj[B_ * H_];
__device__ float g_ctxpart[NT_TC * H_];
__device__ float g_denpart[NT_TC];
__device__ float g_ctx[B_ * H_];
__device__ float g_gates[B_ * 4 * H_];
__device__ float g_wcol[4 * H_];

__device__ __forceinline__ float sigm(float x) { return 1.0f / (1.0f + expf(-x)); }

__device__ __forceinline__ float tanh_fast(float x) {
    float y;
    asm("tanh.approx.f32 %0, %1;" : "=f"(y) : "f"(x));
    return y;
}

__device__ __forceinline__ float warp_sum(float a) {
    #pragma unroll
    for (int o = 16; o > 0; o >>= 1) a += __shfl_xor_sync(0xffffffffu, a, o);
    return a;
}

// bf16 hi/lo split of fp32, packed two-k-per-word (low half = even k)
__device__ __forceinline__ void split2(float x0, float x1, uint32_t& h, uint32_t& l) {
    __nv_bfloat16 h0 = __float2bfloat16(x0), h1 = __float2bfloat16(x1);
    float r0 = x0 - __bfloat162float(h0), r1 = x1 - __bfloat162float(h1);
    __nv_bfloat16 l0 = __float2bfloat16(r0), l1 = __float2bfloat16(r1);
    h = (uint32_t)*(unsigned short*)&h0 | ((uint32_t)*(unsigned short*)&h1 << 16);
    l = (uint32_t)*(unsigned short*)&l0 | ((uint32_t)*(unsigned short*)&l1 << 16);
}

__device__ __forceinline__ void mma_bf16(float* d, uint32_t a0, uint32_t a1,
                                         uint32_t a2, uint32_t a3,
                                         uint32_t b0, uint32_t b1) {
    asm volatile(
        "mma.sync.aligned.m16n8k16.row.col.f32.bf16.bf16.f32 "
        "{%0,%1,%2,%3}, {%4,%5,%6,%7}, {%8,%9}, {%0,%1,%2,%3};"
        : "+f"(d[0]), "+f"(d[1]), "+f"(d[2]), "+f"(d[3])
        : "r"(a0), "r"(a1), "r"(a2), "r"(a3), "r"(b0), "r"(b1));
}

// ---------------------------------------------------------------------------
// K0: q_proj[b][j] = h0[b] @ Wa[j] + ba[j] + bua[j]
// ---------------------------------------------------------------------------
__global__ __launch_bounds__(256)
void k0_qproj(const float* __restrict__ h0, const float* __restrict__ Wa,
              const float* __restrict__ ba, const float* __restrict__ bua) {
    int b = blockIdx.x, tid = threadIdx.x;
    int wid = tid >> 5, lane = tid & 31;
    __shared__ float hs[H_];
    for (int i = tid; i < H_; i += 256) hs[i] = h0[b * H_ + i];
    __syncthreads();
    #pragma unroll 2
    for (int j = wid; j < H_; j += 8) {
        const float* w = Wa + j * H_;
        float a = 0.f;
        for (int k = lane; k < H_; k += 32) a += hs[k] * w[k];
        a = warp_sum(a);
        if (lane == 0) g_qproj[b * H_ + j] = a + ba[j] + bua[j];
    }
}

// ---------------------------------------------------------------------------
// K1 (tensor-core): scores + exp + partial context, bf16 hi/lo split GEMM.
// 128 rows/block, 8 warps * 16 rows * (N=200 = 25 n-tiles of 8), K chunks of
// 16 double-buffered. 3 mma per (ntile, kchunk): AhBh + AhBl + AlBh.
// ---------------------------------------------------------------------------
__global__ __launch_bounds__(256, 1)
void k1_tc(const float* __restrict__ enc, const float* __restrict__ Ua,
           const float* __restrict__ Va) {
    extern __shared__ uint32_t sm[];
    uint32_t* Ah = sm;                        // [128][AS]
    uint32_t* Al = Ah + BMT * AS;             // [128][AS]
    uint32_t* Bh = Al + BMT * AS;             // [2][200*BSW]
    uint32_t* Bl = Bh + 2 * 200 * BSW;        // [2][200*BSW]
    float* qp_s = (float*)(Bl + 2 * 200 * BSW);
    float* va_s = qp_s + H_;
    float* es   = va_s + H_;                  // [128]

    int tid = threadIdx.x;
    int row0 = blockIdx.x * BMT;
    int b = row0 >> 11;                       // T_ = 2048
    const float* encB = enc + (size_t)row0 * H_;

    for (int i = tid; i < H_; i += 256) {
        qp_s[i] = g_qproj[b * H_ + i];
        va_s[i] = Va[i];
    }

    // A: load enc tile, split to bf16 hi/lo (100 packed words per row)
    for (int idx = tid; idx < BMT * 100; idx += 256) {
        int r = idx / 100, kw = idx % 100;
        float2 v = *(const float2*)(encB + r * H_ + kw * 2);
        uint32_t h, l;
        split2(v.x, v.y, h, l);
        Ah[r * AS + kw] = h;
        Al[r * AS + kw] = l;
    }
    for (int idx = tid; idx < BMT * 8; idx += 256) {      // pad k 200..215
        int r = idx / 8, kw = 100 + idx % 8;
        Ah[r * AS + kw] = 0;
        Al[r * AS + kw] = 0;
    }

    // B chunk 0
    for (int idx = tid; idx < 200 * 8; idx += 256) {
        int n = idx >> 3, w = idx & 7;
        float2 v = *(const float2*)(Ua + n * H_ + w * 2); // k = 0..15 < 200
        uint32_t h, l;
        split2(v.x, v.y, h, l);
        Bh[n * BSW + w] = h;
        Bl[n * BSW + w] = l;
    }
    __syncthreads();

    int lane = tid & 31, wid = tid >> 5;
    int grp = lane >> 2, qid = lane & 3;
    int r0 = wid * 16;

    float acc[25][4];
    #pragma unroll
    for (int n = 0; n < 25; n++)
        #pragma unroll
        for (int c = 0; c < 4; c++) acc[n][c] = 0.f;

    for (int kc = 0; kc < NCHUNK; kc++) {
        int buf = kc & 1;
        if (kc) __syncthreads();
        if (kc < NCHUNK - 1) {
            int boff = (buf ^ 1) * 200 * BSW;
            int k0 = (kc + 1) * 16;
            for (int idx = tid; idx < 200 * 8; idx += 256) {
                int n = idx >> 3, w = idx & 7;
                int k = k0 + w * 2;
                uint32_t h = 0, l = 0;
                if (k < H_) {
                    float2 v = *(const float2*)(Ua + n * H_ + k);
                    split2(v.x, v.y, h, l);
                }
                Bh[boff + n * BSW + w] = h;
                Bl[boff + n * BSW + w] = l;
            }
        }
        // A fragments for this chunk
        int abase = (r0 + grp) * AS + kc * 8 + qid;
        uint32_t ah0 = Ah[abase],            ah1 = Ah[abase + 8 * AS];
        uint32_t ah2 = Ah[abase + 4],        ah3 = Ah[abase + 8 * AS + 4];
        uint32_t al0 = Al[abase],            al1 = Al[abase + 8 * AS];
        uint32_t al2 = Al[abase + 4],        al3 = Al[abase + 8 * AS + 4];
        int boff = buf * 200 * BSW;
        #pragma unroll
        for (int nt = 0; nt < 25; nt++) {
            int bb = boff + (nt * 8 + grp) * BSW + qid;
            uint32_t bh0 = Bh[bb], bh1 = Bh[bb + 4];
            uint32_t bl0 = Bl[bb], bl1 = Bl[bb + 4];
            mma_bf16(acc[nt], ah0, ah1, ah2, ah3, bh0, bh1);
            mma_bf16(acc[nt], ah0, ah1, ah2, ah3, bl0, bl1);
            mma_bf16(acc[nt], al0, al1, al2, al3, bh0, bh1);
        }
    }

    // Epilogue: tanh + Va-weighted col reduction -> scores -> exp
    {
        float rsA = 0.f, rsB = 0.f;
        #pragma unroll
        for (int nt = 0; nt < 25; nt++) {
            int c = nt * 8 + qid * 2;
            float v0 = va_s[c], v1 = va_s[c + 1];
            float q0 = qp_s[c], q1 = qp_s[c + 1];
            rsA += v0 * tanh_fast(q0 + acc[nt][0]) + v1 * tanh_fast(q1 + acc[nt][1]);
            rsB += v0 * tanh_fast(q0 + acc[nt][2]) + v1 * tanh_fast(q1 + acc[nt][3]);
        }
        rsA += __shfl_xor_sync(0xffffffffu, rsA, 1);
        rsA += __shfl_xor_sync(0xffffffffu, rsA, 2);
        rsB += __shfl_xor_sync(0xffffffffu, rsB, 1);
        rsB += __shfl_xor_sync(0xffffffffu, rsB, 2);
        if (qid == 0) {
            es[r0 + grp]     = expf(rsA);
            es[r0 + grp + 8] = expf(rsB);
        }
    }
    __syncthreads();

    // Partial context from the bf16 smem copy (Ah+Al ~ enc to 2^-16) + denom
    if (tid < 100) {
        float c0 = 0.f, c1 = 0.f;
        #pragma unroll 4
        for (int r = 0; r < BMT; r++) {
            uint32_t wh = Ah[r * AS + tid], wl = Al[r * AS + tid];
            float x0 = __uint_as_float(wh << 16) + __uint_as_float(wl << 16);
            float x1 = __uint_as_float(wh & 0xffff0000u) + __uint_as_float(wl & 0xffff0000u);
            float e = es[r];
            c0 += e * x0;
            c1 += e * x1;
        }
        g_ctxpart[blockIdx.x * H_ + 2 * tid]     = c0;
        g_ctxpart[blockIdx.x * H_ + 2 * tid + 1] = c1;
    } else if (tid == 224) {
        float s = 0.f;
        #pragma unroll 8
        for (int r = 0; r < BMT; r++) s += es[r];
        g_denpart[blockIdx.x] = s;
    }
}

// ---------------------------------------------------------------------------
// K2: reduce partials -> normalized context. One block per batch.
// ---------------------------------------------------------------------------
__global__ void k2_reduce() {
    int b = blockIdx.x, tid = threadIdx.x;
    __shared__ float dsum;
    if (tid == 0) {
        float s = 0.f;
        #pragma unroll
        for (int t = 0; t < TPB_TC; t++) s += g_denpart[b * TPB_TC + t];
        dsum = 1.0f / s;
    }
    __syncthreads();
    if (tid < H_) {
        float a = 0.f;
        #pragma unroll
        for (int t = 0; t < TPB_TC; t++)
            a += g_ctxpart[(b * TPB_TC + t) * H_ + tid];
        g_ctx[b * H_ + tid] = a * dsum;
    }
}

// ---------------------------------------------------------------------------
// KG: gates GEMM (unchanged from R9).
// ---------------------------------------------------------------------------
#define KG_XPAD 401
__global__ __launch_bounds__(256)
void kg_gates(const float* __restrict__ h0,
              const float* __restrict__ W_ih, const float* __restrict__ W_hh,
              const float* __restrict__ b_ih, const float* __restrict__ b_hh) {
    extern __shared__ float dsm[];
    float* Xs = dsm;                    // [32][401]
    float* As = dsm + 32 * KG_XPAD;     // [8][400]

    int tid = threadIdx.x;
    int b0 = blockIdx.x * 32;
    int j0 = blockIdx.y * 8;

    for (int idx = tid; idx < 32 * H_; idx += 256) {
        int bb = idx / H_, k = idx % H_;
        Xs[bb * KG_XPAD + k]      = h0[(b0 + bb) * H_ + k];
        Xs[bb * KG_XPAD + H_ + k] = g_ctx[(b0 + bb) * H_ + k];
    }
    for (int idx = tid; idx < 8 * H_; idx += 256) {
        int jj = idx / H_, k = idx % H_;
        int j = j0 + jj;
        As[jj * 400 + k]      = W_hh[j * H_ + k];
        As[jj * 400 + H_ + k] = W_ih[j * (H_ + 1) + 1 + k];
        if (k == 0 && blockIdx.x == 0) g_wcol[j] = W_ih[j * (H_ + 1)];
    }
    __syncthreads();

    int jj = tid >> 5;
    int bb = tid & 31;
    int j = j0 + jj;
    const float* a = As + jj * 400;
    const float* xv = Xs + bb * KG_XPAD;
    float acc = b_ih[j] + b_hh[j];
    #pragma unroll 8
    for (int k = 0; k < 400; k++) acc += a[k] * xv[k];
    g_gates[(b0 + bb) * (4 * H_) + j] = acc;
}

// ---------------------------------------------------------------------------
// K4: decode (unchanged from R9).
// ---------------------------------------------------------------------------
#define W1PAD 201
#define W2PAD 101
#define K4_DSM ((100 * W1PAD + 50 * W2PAD) * 4)

__global__ __launch_bounds__(256)
void k4_decode(const float* __restrict__ x_in, const float* __restrict__ c0,
               const float* __restrict__ W1, const float* __restrict__ b1,
               const float* __restrict__ W2, const float* __restrict__ b2,
               const float* __restrict__ W3, const float* __restrict__ b3,
               float* __restrict__ out) {
    extern __shared__ float dsm[];
    float* W1s = dsm;
    float* W2s = dsm + 100 * W1PAD;

    int b = blockIdx.x, tid = threadIdx.x;
    __shared__ float gb[4 * H_], wcol[4 * H_], c0s[H_];
    __shared__ float hr[H_], o1[100], o2[52];
    __shared__ float b1s[100], b2s[52], w3s[52];
    __shared__ float xs;

    for (int j = tid; j < 4 * H_; j += 256) {
        gb[j]   = g_gates[b * (4 * H_) + j];
        wcol[j] = g_wcol[j];
    }
    for (int i = tid; i < H_; i += 256) c0s[i] = c0[b * H_ + i];
    for (int idx = tid; idx < 100 * H_; idx += 256) {
        int r = idx / H_, c = idx % H_;
        W1s[r * W1PAD + c] = W1[idx];
    }
    for (int idx = tid; idx < 50 * 100; idx += 256) {
        int r = idx / 100, c = idx % 100;
        W2s[r * W2PAD + c] = W2[idx];
    }
    if (tid < 100) b1s[tid] = b1[tid];
    if (tid < 50)  b2s[tid] = b2[tid];
    if (tid < 50)  w3s[tid] = W3[tid];
    if (tid == 0)  xs = x_in[b];
    __syncthreads();

    for (int s = 0; s < NS_; s++) {
        float x = xs;
        if (tid < H_) {
            int j = tid;
            float gi = gb[j]           + x * wcol[j];
            float gf = gb[H_ + j]      + x * wcol[H_ + j];
            float gg = gb[2 * H_ + j]  + x * wcol[2 * H_ + j];
            float go = gb[3 * H_ + j]  + x * wcol[3 * H_ + j];
            float c = sigm(gf) * c0s[j] + sigm(gi) * tanhf(gg);
            float h = sigm(go) * tanhf(c);
            hr[j] = fmaxf(h, 0.f);
        }
        __syncthreads();
        if (tid < 100) {
            const float* w = W1s + tid * W1PAD;
            float a = b1s[tid];
            #pragma unroll 8
            for (int k = 0; k < H_; k++) a += w[k] * hr[k];
            o1[tid] = fmaxf(a, 0.f);
        }
        __syncthreads();
        if (tid < 50) {
            const float* w = W2s + tid * W2PAD;
            float a = b2s[tid];
            #pragma unroll 4
            for (int k = 0; k < 100; k++) a += w[k] * o1[k];
            o2[tid] = fmaxf(a, 0.f);
        }
        __syncthreads();
        if (tid < 32) {
            float a = (tid < 50) ? w3s[tid] * o2[tid] : 0.f;
            if (tid < 18) a += w3s[tid + 32] * o2[tid + 32];
            a = warp_sum(a);
            if (tid == 0) {
                float y = a + b3[0];
                out[b * NS_ + s] = y;
                xs = y;
            }
        }
        __syncthreads();
    }
}

// ---------------------------------------------------------------------------
extern "C" void kernel_launch(void* const* d_in, const int* in_sizes, int n_in,
                              void* d_out, int out_size) {
    const float* x    = (const float*)d_in[0];
    const float* h0   = (const float*)d_in[1];
    const float* c0   = (const float*)d_in[2];
    const float* enc  = (const float*)d_in[3];
    const float* Wa   = (const float*)d_in[4];
    const float* ba   = (const float*)d_in[5];
    const float* Ua   = (const float*)d_in[6];
    const float* bua  = (const float*)d_in[7];
    const float* Va   = (const float*)d_in[8];
    // d_in[9] = bva: softmax-invariant, unused.
    const float* W_ih = (const float*)d_in[10];
    const float* W_hh = (const float*)d_in[11];
    const float* b_ih = (const float*)d_in[12];
    const float* b_hh = (const float*)d_in[13];
    const float* W1   = (const float*)d_in[14];
    const float* b1   = (const float*)d_in[15];
    const float* W2   = (const float*)d_in[16];
    const float* b2   = (const float*)d_in[17];
    const float* W3   = (const float*)d_in[18];
    const float* b3   = (const float*)d_in[19];
    float* out = (float*)d_out;

    const int k1_dsm = (BMT * AS * 2 + 2 * 200 * BSW * 2) * 4 + (H_ * 2 + BMT) * 4;
    const int kg_dsm = (32 * KG_XPAD + 8 * 400) * 4;
    cudaFuncSetAttribute(k1_tc, cudaFuncAttributeMaxDynamicSharedMemorySize, k1_dsm);
    cudaFuncSetAttribute(kg_gates, cudaFuncAttributeMaxDynamicSharedMemorySize, kg_dsm);
    cudaFuncSetAttribute(k4_decode, cudaFuncAttributeMaxDynamicSharedMemorySize, K4_DSM);

    k0_qproj<<<B_, 256>>>(h0, Wa, ba, bua);
    k1_tc<<<NT_TC, 256, k1_dsm>>>(enc, Ua, Va);
    k2_reduce<<<B_, 256>>>();
    kg_gates<<<dim3(B_ / 32, (4 * H_) / 8), 256, kg_dsm>>>(h0, W_ih, W_hh, b_ih, b_hh);
    k4_decode<<<B_, 256, K4_DSM>>>(x, c0, W1, b1, W2, b2, W3, b3, out);
}